// round 1
// baseline (speedup 1.0000x reference)
#include <cuda_runtime.h>
#include <stdint.h>

// Shapes (compile-time constants):
//   core0: (1, 50, 8, 16)   -> A[v0][e0][r1]
//   core1: (16, 50, 4, 16)  -> B[r1][v1][e1][r2]
//   core2: (16, 80, 4, 1)   -> C[r2][v2][e2]
//   indices: 8192, vocab 200000 = (50,50,80) row-major
//   out: (8192, 128) fp32, embed multi-index (e0,e1,e2) row-major = e0*16 + e1*4 + e2

#define NV0 50
#define NV1 50
#define NV2 80
#define RANK 16
#define NIDX 8192

// Scratch: H[(v1*80+v2)][r1][e12], 4000 * 16 * 16 floats = 4 MB (resident in L2)
__device__ float g_H[NV1 * NV2 * RANK * 16];

// ---------------------------------------------------------------------------
// Kernel 1: H[p][r1][e1*4+e2] = sum_r2 core1[r1,v1,e1,r2] * core2[r2,v2,e2]
// One block per (v1,v2) pair; 256 threads = one per (r1,e1,e2) output.
// ---------------------------------------------------------------------------
__global__ __launch_bounds__(256) void tt_build_H(
    const float* __restrict__ core1,   // (16,50,4,16)
    const float* __restrict__ core2)   // (16,80,4,1)
{
    const int p  = blockIdx.x;         // v1*80 + v2
    const int v1 = p / NV2;
    const int v2 = p - v1 * NV2;
    const int t  = threadIdx.x;        // 0..255
    const int r1 = t >> 4;
    const int e1 = (t >> 2) & 3;
    const int e2 = t & 3;

    // Stage the 64-float core2 slice C[r2][e2] for this v2 into smem.
    __shared__ float c2[RANK * 4];
    if (t < 64) {
        const int r2 = t >> 2;
        const int ee = t & 3;
        c2[t] = __ldg(&core2[(r2 * NV2 + v2) * 4 + ee]);
    }
    __syncthreads();

    // core1 row: 16 contiguous r2 values.
    const float* b = core1 + (((size_t)r1 * NV1 + v1) * 4 + e1) * RANK;
    float acc = 0.f;
#pragma unroll
    for (int r2 = 0; r2 < RANK; ++r2)
        acc += __ldg(&b[r2]) * c2[r2 * 4 + e2];

    g_H[(size_t)p * (RANK * 16) + r1 * 16 + e1 * 4 + e2] = acc;
}

// ---------------------------------------------------------------------------
// Kernel 2: warp per index. out[n] (128 floats) = A(v0) [8x16] @ H(v1,v2) [16x16]
// Lane l: e0 = l>>2, quarter q = l&3 -> owns out[n][e0*16 + q*4 .. +3] = out[n][l*4..l*4+3]
// Warp store = 512 contiguous bytes.
// ---------------------------------------------------------------------------
__global__ __launch_bounds__(256) void tt_gather(
    const void* __restrict__ idx_raw,
    const float* __restrict__ core0,   // (1,50,8,16)
    float* __restrict__ out)           // (8192,128)
{
    const int gtid = blockIdx.x * blockDim.x + threadIdx.x;
    const int warp = gtid >> 5;
    const int lane = threadIdx.x & 31;
    if (warp >= NIDX) return;

    // --- dtype sniff: int64 vs int32 indices ------------------------------
    // If the buffer is int64 (LE), every high 32-bit word is 0 (values < 2e5).
    // If int32, the first 64 words are random in [0,2e5): P(all 32 sampled
    // odd words == 0) ~ (1/2e5)^32 ~ 0. One load + one ballot per warp.
    const int* i32 = (const int*)idx_raw;
    const int hw = i32[2 * lane + 1];
    const bool is64 = __all_sync(0xffffffffu, hw == 0);

    long long id;
    if (is64) id = ((const long long*)idx_raw)[warp];
    else      id = (long long)i32[warp];

    // Decompose: id = (v0*50 + v1)*80 + v2
    const int iv  = (int)id;
    const int v0  = iv / (NV1 * NV2);
    const int rem = iv - v0 * (NV1 * NV2);
    const int v1  = rem / NV2;
    const int v2  = rem - v1 * NV2;

    const int e0 = lane >> 2;
    const int q  = lane & 3;

    // A row for (v0, e0): 16 contiguous floats over r1. Load as 4x float4.
    const float4* A4 = (const float4*)(core0 + ((size_t)v0 * 8 + e0) * RANK);
    float4 a0 = __ldg(&A4[0]);
    float4 a1 = __ldg(&A4[1]);
    float4 a2 = __ldg(&A4[2]);
    float4 a3 = __ldg(&A4[3]);
    float a[RANK] = { a0.x, a0.y, a0.z, a0.w,  a1.x, a1.y, a1.z, a1.w,
                      a2.x, a2.y, a2.z, a2.w,  a3.x, a3.y, a3.z, a3.w };

    // H slice for (v1,v2): [r1][16], this lane reads float4 at column q*4.
    const float4* H4 = (const float4*)(g_H + ((size_t)(v1 * NV2 + v2)) * (RANK * 16)) + q;

    float4 acc = make_float4(0.f, 0.f, 0.f, 0.f);
#pragma unroll
    for (int r1 = 0; r1 < RANK; ++r1) {
        const float4 h = H4[(size_t)r1 * 4];
        acc.x = fmaf(a[r1], h.x, acc.x);
        acc.y = fmaf(a[r1], h.y, acc.y);
        acc.z = fmaf(a[r1], h.z, acc.z);
        acc.w = fmaf(a[r1], h.w, acc.w);
    }

    ((float4*)(out + (size_t)warp * 128))[lane] = acc;
}

// ---------------------------------------------------------------------------
// Launch
// Inputs (metadata order): indices, core0, core1, core2
// ---------------------------------------------------------------------------
extern "C" void kernel_launch(void* const* d_in, const int* in_sizes, int n_in,
                              void* d_out, int out_size)
{
    const void*  indices = d_in[0];
    const float* core0   = (const float*)d_in[1];
    const float* core1   = (const float*)d_in[2];
    const float* core2   = (const float*)d_in[3];
    float* out = (float*)d_out;

    tt_build_H<<<NV1 * NV2, 256>>>(core1, core2);
    tt_gather<<<(NIDX * 32) / 256, 256>>>(indices, core0, out);
}

// round 2
// speedup vs baseline: 1.0833x; 1.0833x over previous
#include <cuda_runtime.h>
#include <stdint.h>

// Shapes:
//   core0: (1, 50, 8, 16)   -> A[v0][e0][r1]
//   core1: (16, 50, 4, 16)  -> B[r1][v1][e1][r2]
//   core2: (16, 80, 4, 1)   -> C[r2][v2][e2]
//   indices: 8192, vocab 200000 = (50,50,80) row-major
//   out: (8192, 128) fp32, embed index = e0*16 + e1*4 + e2

#define NV0 50
#define NV1 50
#define NV2 80
#define RANK 16
#define NIDX 8192

// Fused kernel: one warp per index.
//   Phase 1: warp builds H[r1][e1*4+e2] (16x16) in smem:
//            H[r1][e12] = sum_r2 B[r1,v1,e1,r2] * C[r2,v2,e2]
//            lane l handles entries idx = k*32+l (k=0..7): r1=2k+(l>>4),
//            e1=(l>>2)&3, e2=l&3  -> 8 entries x 16 FMA each.
//   Phase 2: lane l (e0=l>>2, q=l&3) computes out[e0][q*4..q*4+3]
//            = sum_r1 A[e0][r1] * H[r1][q*4..q*4+3]; warp store = 512B contig.
__global__ __launch_bounds__(256) void tt_fused(
    const void* __restrict__ idx_raw,
    const float* __restrict__ core0,
    const float* __restrict__ core1,
    const float* __restrict__ core2,
    float* __restrict__ out)
{
    // Per-warp smem: [0..63] = C slice (r2-major, [r2*4+e2]); [64..319] = H.
    __shared__ __align__(16) float sh[8][320];

    const int w    = threadIdx.x >> 5;
    const int lane = threadIdx.x & 31;
    const int warp = blockIdx.x * 8 + w;      // index id, grid is exact

    // --- dtype sniff: int64 vs int32 indices (values < 2e5) ---------------
    const int* i32 = (const int*)idx_raw;
    const int hw = i32[2 * lane + 1];
    const bool is64 = __all_sync(0xffffffffu, hw == 0);

    int iv;
    if (is64) iv = (int)((const long long*)idx_raw)[warp];
    else      iv = i32[warp];

    // id = (v0*50 + v1)*80 + v2
    const int v0  = iv / (NV1 * NV2);
    const int rem = iv - v0 * (NV1 * NV2);
    const int v1  = rem / NV2;
    const int v2  = rem - v1 * NV2;

    const int e2 = lane & 3;
    const int e1 = (lane >> 2) & 3;
    const int b  = lane >> 4;          // r1 low bit source
    const int e0 = lane >> 2;          // phase-2 row
    const int q  = lane & 3;           // phase-2 column quarter

    // Kick off A loads early (phase-2 operand): 16 contiguous floats.
    const float4* A4 = (const float4*)(core0 + ((size_t)v0 * 8 + e0) * RANK);
    const float4 a0 = __ldg(&A4[0]);
    const float4 a1 = __ldg(&A4[1]);
    const float4 a2 = __ldg(&A4[2]);
    const float4 a3 = __ldg(&A4[3]);

    // Stage C slice: 16 lanes each load one float4 row C[r2][0..3].
    if (lane < RANK) {
        const float4 c = __ldg((const float4*)(core2 + ((size_t)lane * NV2 + v2) * 4));
        *(float4*)&sh[w][lane * 4] = c;
    }
    __syncwarp();

    // Pull this lane's C column (fixed e2) into registers.
    float c2c[RANK];
#pragma unroll
    for (int r2 = 0; r2 < RANK; ++r2) c2c[r2] = sh[w][r2 * 4 + e2];
    __syncwarp();

    // Phase 1: 8 H entries per lane.
#pragma unroll
    for (int k = 0; k < 8; ++k) {
        const int r1 = 2 * k + b;
        const float4* B4 = (const float4*)(core1 + (((size_t)r1 * NV1 + v1) * 4 + e1) * RANK);
        const float4 b0 = __ldg(&B4[0]);
        const float4 b1 = __ldg(&B4[1]);
        const float4 b2 = __ldg(&B4[2]);
        const float4 b3 = __ldg(&B4[3]);
        float acc;
        acc = b0.x * c2c[0];
        acc = fmaf(b0.y, c2c[1],  acc);
        acc = fmaf(b0.z, c2c[2],  acc);
        acc = fmaf(b0.w, c2c[3],  acc);
        acc = fmaf(b1.x, c2c[4],  acc);
        acc = fmaf(b1.y, c2c[5],  acc);
        acc = fmaf(b1.z, c2c[6],  acc);
        acc = fmaf(b1.w, c2c[7],  acc);
        acc = fmaf(b2.x, c2c[8],  acc);
        acc = fmaf(b2.y, c2c[9],  acc);
        acc = fmaf(b2.z, c2c[10], acc);
        acc = fmaf(b2.w, c2c[11], acc);
        acc = fmaf(b3.x, c2c[12], acc);
        acc = fmaf(b3.y, c2c[13], acc);
        acc = fmaf(b3.z, c2c[14], acc);
        acc = fmaf(b3.w, c2c[15], acc);
        sh[w][64 + k * 32 + lane] = acc;   // = H[r1][e1*4+e2], bank = lane
    }
    __syncwarp();

    // Phase 2: out[e0][q*4..+3] = sum_r1 A[e0][r1] * H[r1][q*4..+3]
    const float a[RANK] = { a0.x, a0.y, a0.z, a0.w,  a1.x, a1.y, a1.z, a1.w,
                            a2.x, a2.y, a2.z, a2.w,  a3.x, a3.y, a3.z, a3.w };
    float4 acc = make_float4(0.f, 0.f, 0.f, 0.f);
#pragma unroll
    for (int r1 = 0; r1 < RANK; ++r1) {
        const float4 h = *(const float4*)&sh[w][64 + r1 * 16 + q * 4];
        acc.x = fmaf(a[r1], h.x, acc.x);
        acc.y = fmaf(a[r1], h.y, acc.y);
        acc.z = fmaf(a[r1], h.z, acc.z);
        acc.w = fmaf(a[r1], h.w, acc.w);
    }

    ((float4*)(out + (size_t)warp * 128))[lane] = acc;
}

// Inputs (metadata order): indices, core0, core1, core2
extern "C" void kernel_launch(void* const* d_in, const int* in_sizes, int n_in,
                              void* d_out, int out_size)
{
    const void*  indices = d_in[0];
    const float* core0   = (const float*)d_in[1];
    const float* core1   = (const float*)d_in[2];
    const float* core2   = (const float*)d_in[3];
    float* out = (float*)d_out;

    tt_fused<<<NIDX / 8, 256>>>(indices, core0, core1, core2, out);
}

// round 3
// speedup vs baseline: 1.6041x; 1.4807x over previous
#include <cuda_runtime.h>
#include <stdint.h>

// Shapes:
//   core0: (1, 50, 8, 16)   -> A[v0][e0][r1]
//   core1: (16, 50, 4, 16)  -> B[r1][v1][e1][r2]
//   core2: (16, 80, 4, 1)   -> C[r2][v2][e2]
//   indices: 8192, vocab 200000 = (50,50,80) row-major
//   out: (8192, 128) fp32, embed index = e0*16 + e1*4 + e2

#define NV0 50
#define NV1 50
#define NV2 80
#define RANK 16
#define NIDX 8192

// H[(v1*80+v2)][r1][e1*4+e2]: 4000 * 256 floats = 4 MB (L2-resident)
__device__ float g_H[NV1 * NV2 * RANK * 16];

// ---------------------------------------------------------------------------
// Kernel 1: warp per (v1,v2) pair. Lane owns two B rows (r1,e1); C slice is
// staged in smem and read as LDS.128 broadcast. H stored as coalesced float4.
//   H[r1][e1*4+e2] = sum_r2 B[r1,v1,e1,r2] * C[r2,v2,e2]
// ---------------------------------------------------------------------------
__global__ __launch_bounds__(256) void tt_build_H(
    const float* __restrict__ core1,   // (16,50,4,16)
    const float* __restrict__ core2)   // (16,80,4,1)
{
    __shared__ __align__(16) float sc[8][64];   // per-warp C slice [r2*4+e2]

    const int w    = threadIdx.x >> 5;
    const int lane = threadIdx.x & 31;
    const int pair = blockIdx.x * 8 + w;        // 0..3999, grid exact
    const int v1   = pair / NV2;
    const int v2   = pair - v1 * NV2;

    // Stage C slice: lane r2<16 loads C[r2][v2][0..3] as one float4.
    if (lane < RANK) {
        const float4 c = __ldg((const float4*)(core2 + ((size_t)lane * NV2 + v2) * 4));
        *(float4*)&sc[w][lane * 4] = c;
    }
    __syncwarp();

    float* hout = g_H + (size_t)pair * (RANK * 16);

#pragma unroll
    for (int pass = 0; pass < 2; ++pass) {
        const int j  = lane + 32 * pass;        // row id 0..63
        const int r1 = j >> 2;
        const int e1 = j & 3;

        // B row (16 floats), no duplication across lanes, 4-lane coalesced.
        const float4* B4 = (const float4*)(core1 + (((size_t)r1 * NV1 + v1) * 4 + e1) * RANK);
        const float4 b0 = __ldg(&B4[0]);
        const float4 b1 = __ldg(&B4[1]);
        const float4 b2 = __ldg(&B4[2]);
        const float4 b3 = __ldg(&B4[3]);
        const float bb[RANK] = { b0.x, b0.y, b0.z, b0.w,  b1.x, b1.y, b1.z, b1.w,
                                 b2.x, b2.y, b2.z, b2.w,  b3.x, b3.y, b3.z, b3.w };

        float4 acc = make_float4(0.f, 0.f, 0.f, 0.f);
#pragma unroll
        for (int r2 = 0; r2 < RANK; ++r2) {
            const float4 c4 = *(const float4*)&sc[w][r2 * 4];   // broadcast LDS.128
            acc.x = fmaf(bb[r2], c4.x, acc.x);
            acc.y = fmaf(bb[r2], c4.y, acc.y);
            acc.z = fmaf(bb[r2], c4.z, acc.z);
            acc.w = fmaf(bb[r2], c4.w, acc.w);
        }
        // H[r1][e1*4 .. +3] = acc -> float4 index j, perfectly coalesced STG.128
        ((float4*)hout)[j] = acc;
    }
}

// ---------------------------------------------------------------------------
// Kernel 2: warp per index. out = A(v0) [8x16] @ H(v1,v2) [16x16].
// Lane l: e0=l>>2, q=l&3 owns out[l*4 .. l*4+3]. All 20 loads issued up front.
// ---------------------------------------------------------------------------
__global__ __launch_bounds__(256) void tt_gather(
    const void* __restrict__ idx_raw,
    const float* __restrict__ core0,   // (1,50,8,16)
    float* __restrict__ out)           // (8192,128)
{
    const int gtid = blockIdx.x * blockDim.x + threadIdx.x;
    const int warp = gtid >> 5;
    const int lane = threadIdx.x & 31;

    // dtype sniff: int64 vs int32 (all values < 2e5 -> high words all zero)
    const int* i32 = (const int*)idx_raw;
    const int hw = i32[2 * lane + 1];
    const bool is64 = __all_sync(0xffffffffu, hw == 0);

    int iv;
    if (is64) iv = (int)((const long long*)idx_raw)[warp];
    else      iv = i32[warp];

    const int v0  = iv / (NV1 * NV2);
    const int rem = iv - v0 * (NV1 * NV2);
    const int v1  = rem / NV2;
    const int v2  = rem - v1 * NV2;

    const int e0 = lane >> 2;
    const int q  = lane & 3;

    // A row (16 floats over r1)
    const float4* A4 = (const float4*)(core0 + ((size_t)v0 * 8 + e0) * RANK);
    // H tile quarter-column: float4 at (r1*16 + q*4)
    const float4* H4 = (const float4*)(g_H + ((size_t)(v1 * NV2 + v2)) * (RANK * 16)) + q;

    // Issue everything up front for max MLP.
    float4 h[RANK];
#pragma unroll
    for (int r1 = 0; r1 < RANK; ++r1) h[r1] = __ldg(&H4[(size_t)r1 * 4]);
    const float4 a0 = __ldg(&A4[0]);
    const float4 a1 = __ldg(&A4[1]);
    const float4 a2 = __ldg(&A4[2]);
    const float4 a3 = __ldg(&A4[3]);
    const float a[RANK] = { a0.x, a0.y, a0.z, a0.w,  a1.x, a1.y, a1.z, a1.w,
                            a2.x, a2.y, a2.z, a2.w,  a3.x, a3.y, a3.z, a3.w };

    float4 acc = make_float4(0.f, 0.f, 0.f, 0.f);
#pragma unroll
    for (int r1 = 0; r1 < RANK; ++r1) {
        acc.x = fmaf(a[r1], h[r1].x, acc.x);
        acc.y = fmaf(a[r1], h[r1].y, acc.y);
        acc.z = fmaf(a[r1], h[r1].z, acc.z);
        acc.w = fmaf(a[r1], h[r1].w, acc.w);
    }

    ((float4*)(out + (size_t)warp * 128))[lane] = acc;
}

// Inputs (metadata order): indices, core0, core1, core2
extern "C" void kernel_launch(void* const* d_in, const int* in_sizes, int n_in,
                              void* d_out, int out_size)
{
    const void*  indices = d_in[0];
    const float* core0   = (const float*)d_in[1];
    const float* core1   = (const float*)d_in[2];
    const float* core2   = (const float*)d_in[3];
    float* out = (float*)d_out;

    tt_build_H<<<(NV1 * NV2) / 8, 256>>>(core1, core2);
    tt_gather<<<(NIDX * 32) / 256, 256>>>(indices, core0, out);
}